// round 1
// baseline (speedup 1.0000x reference)
#include <cuda_runtime.h>

// Shapes fixed by the problem: x,f = (B=2, 3, T=5, H=720, W=1280) fp32.
// Output = concat(ow, xw), each (B,3,T,H,W) fp32.
constexpr int B  = 2;
constexpr int C  = 3;
constexpr int T  = 5;
constexpr int H  = 720;
constexpr int W  = 1280;
constexpr long PLANE = (long)H * W;          // 921,600
constexpr long CH    = (long)T * PLANE;      // stride between channels: T*H*W
constexpr long HALF  = (long)B * C * CH;     // 27,648,000 (size of one output tensor)
constexpr long NPIX  = (long)B * T * PLANE;  // 9,216,000 pixels

__global__ __launch_bounds__(256)
void ImageBWarp_65343632441725_kernel(const float* __restrict__ x,
                                      const float* __restrict__ f,
                                      float* __restrict__ out)
{
    long idx = (long)blockIdx.x * blockDim.x + threadIdx.x;
    if (idx >= NPIX) return;

    int w = (int)(idx % W);
    long tmp = idx / W;
    int h = (int)(tmp % H);
    tmp /= H;
    int t = (int)(tmp % T);
    int b = (int)(tmp / T);

    long hw = (long)h * W + w;
    long bt = ((long)b * C * T + t) * PLANE;   // base for (b, c=0, t) plane

    // flow + weight logit (coalesced planar loads)
    const float* fb = f + bt + hw;
    float fx = __ldg(fb);
    float fy = __ldg(fb + CH);
    float wl = __ldg(fb + 2 * CH);
    float weight = 1.0f / (1.0f + expf(-wl));

    // align_corners grid algebra collapses to pure pixel offsets
    float gx = (float)w + fx;
    float gy = (float)h + fy;

    float x0f = floorf(gx);
    float y0f = floorf(gy);
    float wx1 = gx - x0f;
    float wy1 = gy - y0f;
    float wx0 = 1.0f - wx1;
    float wy0 = 1.0f - wy1;

    int ix0 = (int)x0f;
    int iy0 = (int)y0f;
    int ix1 = ix0 + 1;
    int iy1 = iy0 + 1;

    // validity (zeros padding): unsigned-compare trick handles negatives
    bool vx0 = (unsigned)ix0 < (unsigned)W;
    bool vx1 = (unsigned)ix1 < (unsigned)W;
    bool vy0 = (unsigned)iy0 < (unsigned)H;
    bool vy1 = (unsigned)iy1 < (unsigned)H;

    float m00 = (vx0 && vy0) ? wx0 * wy0 : 0.0f;
    float m10 = (vx1 && vy0) ? wx1 * wy0 : 0.0f;
    float m01 = (vx0 && vy1) ? wx0 * wy1 : 0.0f;
    float m11 = (vx1 && vy1) ? wx1 * wy1 : 0.0f;

    // clamped indices — loads are always in-bounds, invalid corners weighted 0
    int cx0 = min(max(ix0, 0), W - 1);
    int cx1 = min(max(ix1, 0), W - 1);
    int cy0 = min(max(iy0, 0), H - 1);
    int cy1 = min(max(iy1, 0), H - 1);

    long o00 = (long)cy0 * W + cx0;
    long o10 = (long)cy0 * W + cx1;
    long o01 = (long)cy1 * W + cx0;
    long o11 = (long)cy1 * W + cx1;

    float cov = m00 + m10 + m01 + m11;
    float ow_val = weight * cov;

    const float* xb = x + bt;
    float* out_ow = out + bt + hw;
    float* out_xw = out_ow + HALF;

#pragma unroll
    for (int c = 0; c < C; c++) {
        const float* xc = xb + (long)c * CH;
        float s = m00 * __ldg(xc + o00)
                + m10 * __ldg(xc + o10)
                + m01 * __ldg(xc + o01)
                + m11 * __ldg(xc + o11);
        out_ow[(long)c * CH] = ow_val;       // all 3 ow channels identical
        out_xw[(long)c * CH] = weight * s;
    }
}

extern "C" void kernel_launch(void* const* d_in, const int* in_sizes, int n_in,
                              void* d_out, int out_size)
{
    const float* x = (const float*)d_in[0];
    const float* f = (const float*)d_in[1];
    float* out = (float*)d_out;

    const int threads = 256;
    const long blocks = (NPIX + threads - 1) / threads;
    ImageBWarp_65343632441725_kernel<<<(unsigned)blocks, threads>>>(x, f, out);
}